// round 7
// baseline (speedup 1.0000x reference)
#include <cuda_runtime.h>
#include <cstdint>

#define B_   64
#define T_   512
#define H_   512
#define E_   128
#define C_   1000
#define G7   (7 * H_)    // 3584
#define OUTW (6 * H_)    // 3072
#define NCTA 128
#define NTHR 1024

typedef unsigned long long ull;

// ---- device-global scratch ----
__device__ float g_tg[C_ * G7];        // table_gates = emb @ W1 + b   (14.3 MB)
__device__ float g_h[2][H_ * B_];      // h_d double buffer, [buf][k*64+b]
__device__ int           g_count;
__device__ volatile int  g_sense;

// ---- helpers ----
__device__ __forceinline__ float sigf(float x)      { return 1.0f / (1.0f + expf(-x)); }
__device__ __forceinline__ float softplusf(float x) { return fmaxf(x, 0.0f) + log1pf(expf(-fabsf(x))); }

__device__ __forceinline__ void ffma2(ull& d, ull a, ull b)
{
    asm("fma.rn.f32x2 %0, %1, %2, %0;" : "+l"(d) : "l"(a), "l"(b));
}

__device__ __forceinline__ uint32_t smem_u32(const void* p)
{
    uint32_t a;
    asm("{ .reg .u64 t; cvta.to.shared.u64 t, %1; cvt.u32.u64 %0, t; }" : "=r"(a) : "l"(p));
    return a;
}

__device__ __forceinline__ void mbar_init(uint32_t mbar, uint32_t cnt)
{
    asm volatile("mbarrier.init.shared.b64 [%0], %1;" :: "r"(mbar), "r"(cnt) : "memory");
}
__device__ __forceinline__ void mbar_expect_tx(uint32_t mbar, uint32_t bytes)
{
    asm volatile("mbarrier.arrive.expect_tx.shared.b64 _, [%0], %1;" :: "r"(mbar), "r"(bytes) : "memory");
}
__device__ __forceinline__ void bulk_ldgsts(uint32_t dst, const void* src, uint32_t bytes, uint32_t mbar)
{
    asm volatile("cp.async.bulk.shared::cta.global.mbarrier::complete_tx::bytes [%0], [%1], %2, [%3];"
                 :: "r"(dst), "l"(src), "r"(bytes), "r"(mbar) : "memory");
}
__device__ __forceinline__ void mbar_wait(uint32_t mbar, uint32_t parity)
{
    uint32_t done;
    asm volatile(
        "{\n\t.reg .pred p;\n\t"
        "mbarrier.try_wait.parity.acquire.cta.shared::cta.b64 p, [%1], %2;\n\t"
        "selp.b32 %0, 1, 0, p;\n\t}"
        : "=r"(done) : "r"(mbar), "r"(parity) : "memory");
    if (!done) {
        asm volatile(
            "{\n\t.reg .pred P1;\n\t"
            "WL_%=:\n\t"
            "mbarrier.try_wait.parity.acquire.cta.shared::cta.b64 P1, [%0], %1, 0x989680;\n\t"
            "@P1 bra.uni WD_%=;\n\t"
            "bra.uni WL_%=;\n\t"
            "WD_%=:\n\t}"
            :: "r"(mbar), "r"(parity) : "memory");
    }
}

__device__ __forceinline__ void grid_sync(int* sense)
{
    __threadfence();
    __syncthreads();
    if (threadIdx.x == 0) {
        int s = *sense ^ 1;
        *sense = s;
        if (atomicAdd(&g_count, 1) == (int)gridDim.x - 1) {
            g_count = 0;
            __threadfence();
            g_sense = s;
        } else {
            while (g_sense != s) { __nanosleep(64); }
            __threadfence();
        }
    }
    __syncthreads();
}

// =====================  Kernel 1: table_gates  =====================
__global__ void tg_kernel(const float* __restrict__ emb,
                          const float* __restrict__ W,
                          const float* __restrict__ bias)
{
    __shared__ float sh_e[16][E_];
    const int col = blockIdx.x * 256 + threadIdx.x;
    const int c0  = blockIdx.y * 16;

    for (int i = threadIdx.x; i < 16 * E_; i += 256) {
        int ci = i >> 7, e = i & 127;
        int c  = c0 + ci;
        sh_e[ci][e] = (c < C_) ? emb[c * E_ + e] : 0.0f;
    }
    __syncthreads();

    float acc[16];
#pragma unroll
    for (int i = 0; i < 16; ++i) acc[i] = 0.0f;

    for (int e = 0; e < E_; ++e) {
        float wv = W[e * G7 + col];
#pragma unroll
        for (int i = 0; i < 16; ++i) acc[i] = fmaf(sh_e[i][e], wv, acc[i]);
    }
    float bb = bias[col];
#pragma unroll
    for (int i = 0; i < 16; ++i) {
        int c = c0 + i;
        if (c < C_) g_tg[c * G7 + col] = acc[i] + bb;
    }
}

// =====================  Kernel 2: persistent recurrence  =====================
// 128 CTAs x 1024 threads. CTA owns j in [4*cta, 4*cta+4) (28 gate cols).
// tid = ks*64 + r ; ks 0..15 (K-split 16) ; r = bq*4 + jl.
// Warp = 8 b-quads x 4 jl: W LDS broadcast across quads, h LDS broadcast across jl.
// W dup-pair float2 smem [k][jl][g pad8] (128KB resident).
// h staged via cp.async.bulk, 2 x 32KB double-buffered chunks (k-chunks of 128).
// Reduction records alias the h buffers after compute.
#define W_U     (512 * 32)                 // 16384 ull = 131072 B
#define HB_F    (128 * 64)                 // 8192 floats = 32768 B per buffer
#define HBUF_BYTES 32768
#define SMEM_MAIN  (W_U * 8 + 2 * HBUF_BYTES)   // 196608
#define MBAR_OFF   SMEM_MAIN
#define SMEM_BYTES (SMEM_MAIN + 64)
#define RSTRIDE 30                          // floats per reduction record

__global__ void __launch_bounds__(NTHR, 1)
rec_kernel(const int*   __restrict__ marks,
           const float* __restrict__ ts,
           const float* __restrict__ Wc,
           const float* __restrict__ init,
           float*       __restrict__ out)
{
    extern __shared__ float smem[];
    ull*   sh_W  = (ull*)smem;                       // [k][jl][g8] dup pairs
    float* sh_hb = smem + W_U * 2;                   // 2 x 32KB chunk buffers
    float* sh_red = sh_hb;                           // alias after compute
    const uint32_t mb0 = smem_u32((char*)smem + MBAR_OFF);
    const uint32_t mb1 = mb0 + 8;

    const int tid = threadIdx.x;
    const int cta = blockIdx.x;
    const int ks  = tid >> 6;        // 0..15
    const int r   = tid & 63;
    const int jl  = r & 3;
    const int q4  = (r >> 2) * 4;

    // epilogue identity (threads 0..255): one (b, j) each
    const int eb  = tid >> 2;        // 0..63
    const int ejl = tid & 3;
    const int ej  = cta * 4 + ejl;

    // ---- mbarrier init ----
    if (tid == 0) { mbar_init(mb0, 1); mbar_init(mb1, 1); }

    // ---- load resident W slice: [k][jl][g pad8] dup pairs ----
    {
        float2* Wp = (float2*)sh_W;
        for (int idx = tid; idx < W_U; idx += NTHR) {
            int k = idx >> 5; int rem = idx & 31;
            int jj = rem >> 3, g = rem & 7;
            float w = (g < 7) ? Wc[(size_t)(E_ + k) * G7 + g * H_ + cta * 4 + jj] : 0.0f;
            Wp[idx] = make_float2(w, w);
        }
    }

    // ---- init h buffer ----
    for (int idx = tid; idx < 4 * 64; idx += NTHR) {
        int jj = idx >> 6, bb = idx & 63;
        g_h[0][(cta * 4 + jj) * B_ + bb] = tanhf(init[cta * 4 + jj]);
    }

    // ---- output row t=0 ----
    for (int idx = tid; idx < 4 * 6 * 64; idx += NTHR) {
        int bb = idx & 63; int rest = idx >> 6;
        int f = rest % 6; int jj = rest / 6;
        int jg = cta * 4 + jj;
        float v;
        switch (f) {
            case 0:  v = tanhf(init[0 * H_ + jg]);     break;
            case 1:  v = sigf (init[5 * H_ + jg]);     break;
            case 2:  v = tanhf(init[2 * H_ + jg]);     break;
            case 3:  v = tanhf(init[3 * H_ + jg]);     break;
            case 4:  v = softplusf(init[4 * H_ + jg]); break;
            default: v = tanhf(init[1 * H_ + jg]);     break;
        }
        out[(size_t)bb * (513 * OUTW) + f * H_ + jg] = v;
    }

    // ---- per-(b,j) recurrent state (epilogue threads) ----
    float c_d = tanhf(init[H_ + ej]);
    float c_b = tanhf(init[2 * H_ + ej]);

    int sense = 0;
    int ph0 = 0, ph1 = 0;
    grid_sync(&sense);   // 1 + 511 = 512 flips (even -> graph replay safe)

    const uint32_t hb_u32_0 = smem_u32(sh_hb);
    const uint32_t hb_u32_1 = hb_u32_0 + HBUF_BYTES;

#define STEP(hp, wp) do {                                                       \
        ulonglong2 hh  = *(const ulonglong2*)(hp);                              \
        ulonglong2 w01 = *(const ulonglong2*)(wp);                              \
        ulonglong2 w23 = *(const ulonglong2*)((wp) + 2);                        \
        ulonglong2 w45 = *(const ulonglong2*)((wp) + 4);                        \
        ull        w6  = (wp)[6];                                               \
        ffma2(acc[0],  w01.x, hh.x); ffma2(acc[1],  w01.x, hh.y);               \
        ffma2(acc[2],  w01.y, hh.x); ffma2(acc[3],  w01.y, hh.y);               \
        ffma2(acc[4],  w23.x, hh.x); ffma2(acc[5],  w23.x, hh.y);               \
        ffma2(acc[6],  w23.y, hh.x); ffma2(acc[7],  w23.y, hh.y);               \
        ffma2(acc[8],  w45.x, hh.x); ffma2(acc[9],  w45.x, hh.y);               \
        ffma2(acc[10], w45.y, hh.x); ffma2(acc[11], w45.y, hh.y);               \
        ffma2(acc[12], w6,    hh.x); ffma2(acc[13], w6,    hh.y);               \
    } while (0)

    for (int t = 0; t < T_; ++t) {
        const char* hsrc = (const char*)&g_h[t & 1][0];

        // ---- kick off chunk 0 and 1 TMA bulk loads ----
        if (tid == 0) {
            mbar_expect_tx(mb0, HBUF_BYTES);
            bulk_ldgsts(hb_u32_0, hsrc, HBUF_BYTES, mb0);
            mbar_expect_tx(mb1, HBUF_BYTES);
            bulk_ldgsts(hb_u32_1, hsrc + HBUF_BYTES, HBUF_BYTES, mb1);
        }

        // ---- epilogue prefetch (long-latency, consumed after matmul) ----
        float tsv = 0.f, tsp = 0.f, tg[7];
        if (tid < 256) {
            int m = __ldg(&marks[eb * T_ + t]);
            tsv   = __ldg(&ts[eb * T_ + t]);
            tsp   = (t > 0) ? __ldg(&ts[eb * T_ + t - 1]) : 0.0f;
            const float* tgp = g_tg + (size_t)m * G7 + ej;
#pragma unroll
            for (int g = 0; g < 7; ++g) tg[g] = __ldcg(tgp + g * H_);
        }

        ull acc[14];
#pragma unroll
        for (int i = 0; i < 14; ++i) acc[i] = 0ull;

        // chunk 0 : k 0..127
        mbar_wait(mb0, ph0); ph0 ^= 1;
        {
            const float* hp = sh_hb + (ks * 8) * 64 + q4;
            const ull*   wp = sh_W + (size_t)((0 * 128 + ks * 8) * 4 + jl) * 8;
#pragma unroll
            for (int m = 0; m < 8; ++m) { STEP(hp, wp); hp += 64; wp += 32; }
        }
        __syncthreads();
        if (tid == 0) { mbar_expect_tx(mb0, HBUF_BYTES); bulk_ldgsts(hb_u32_0, hsrc + 2 * HBUF_BYTES, HBUF_BYTES, mb0); }

        // chunk 1 : k 128..255
        mbar_wait(mb1, ph1); ph1 ^= 1;
        {
            const float* hp = sh_hb + HB_F + (ks * 8) * 64 + q4;
            const ull*   wp = sh_W + (size_t)((1 * 128 + ks * 8) * 4 + jl) * 8;
#pragma unroll
            for (int m = 0; m < 8; ++m) { STEP(hp, wp); hp += 64; wp += 32; }
        }
        __syncthreads();
        if (tid == 0) { mbar_expect_tx(mb1, HBUF_BYTES); bulk_ldgsts(hb_u32_1, hsrc + 3 * HBUF_BYTES, HBUF_BYTES, mb1); }

        // chunk 2 : k 256..383
        mbar_wait(mb0, ph0); ph0 ^= 1;
        {
            const float* hp = sh_hb + (ks * 8) * 64 + q4;
            const ull*   wp = sh_W + (size_t)((2 * 128 + ks * 8) * 4 + jl) * 8;
#pragma unroll
            for (int m = 0; m < 8; ++m) { STEP(hp, wp); hp += 64; wp += 32; }
        }
        __syncthreads();   // buf0 fully consumed (recs will alias it)

        // chunk 3 : k 384..511
        mbar_wait(mb1, ph1); ph1 ^= 1;
        {
            const float* hp = sh_hb + HB_F + (ks * 8) * 64 + q4;
            const ull*   wp = sh_W + (size_t)((3 * 128 + ks * 8) * 4 + jl) * 8;
#pragma unroll
            for (int m = 0; m < 8; ++m) { STEP(hp, wp); hp += 64; wp += 32; }
        }
        __syncthreads();   // all chunks consumed -> safe to alias as reduction recs

        // ---- reduction round 1: upper half (ks 8..15) write records ----
        if (tid >= 512) {
            ull* rb = (ull*)(sh_red + (size_t)(tid - 512) * RSTRIDE);
#pragma unroll
            for (int i = 0; i < 14; ++i) rb[i] = acc[i];
        }
        __syncthreads();

        // ---- round 2: lower half adds partner, rewrites its own record ----
        if (tid < 512) {
            float2* af = (float2*)acc;
            const float2* rp = (const float2*)(sh_red + (size_t)tid * RSTRIDE);
#pragma unroll
            for (int i = 0; i < 14; ++i) {
                float2 v = rp[i];
                af[i].x += v.x; af[i].y += v.y;
            }
            ull* rb = (ull*)(sh_red + (size_t)tid * RSTRIDE);
#pragma unroll
            for (int i = 0; i < 14; ++i) rb[i] = acc[i];
        }
        __syncthreads();

        // ---- epilogue: 256 threads, one (b, j) each ----
        if (tid < 256) {
            const int r_src = ((eb >> 2) << 2) | ejl;
            const int fidx  = (eb & 3);
            float a[7];
#pragma unroll
            for (int g = 0; g < 7; ++g) a[g] = 0.0f;
#pragma unroll
            for (int s = 0; s < 8; ++s) {
                const float* rp = sh_red + (size_t)(s * 64 + r_src) * RSTRIDE;
#pragma unroll
                for (int g = 0; g < 7; ++g) a[g] += rp[g * 4 + fidx];
            }

            float dur = tsv - tsp;
            float gi  = sigf (a[0] + tg[0]);
            float gf  = sigf (a[1] + tg[1]);
            float gz  = tanhf(a[2] + tg[2]);
            float go  = sigf (a[3] + tg[3]);
            float gib = sigf (a[4] + tg[4]);
            float gfb = sigf (a[5] + tg[5]);
            float gd  = softplusf(a[6] + tg[6]);

            float c  = gf * c_d + gi * gz;
            float cb = gfb * c_b + gib * gz;
            float cd = cb + (c - cb) * expf(-gd * dur);
            float hd = go * tanhf(cd);
            c_d = cd; c_b = cb;

            size_t ob = (size_t)eb * (513 * OUTW) + (size_t)(t + 1) * OUTW + ej;
            out[ob]          = hd;
            out[ob + 1 * H_] = go;
            out[ob + 2 * H_] = cb;
            out[ob + 3 * H_] = c;
            out[ob + 4 * H_] = gd;
            out[ob + 5 * H_] = cd;

            g_h[(t + 1) & 1][ej * B_ + eb] = hd;
        }

        if (t != T_ - 1) grid_sync(&sense);
    }
#undef STEP
}

// =====================  launch  =====================
extern "C" void kernel_launch(void* const* d_in, const int* in_sizes, int n_in,
                              void* d_out, int out_size)
{
    const int*   marks = (const int*)  d_in[0];
    const float* ts    = (const float*)d_in[1];
    const float* emb   = (const float*)d_in[2];
    const float* Wc    = (const float*)d_in[3];
    const float* bc    = (const float*)d_in[4];
    const float* init  = (const float*)d_in[5];
    float*       out   = (float*)d_out;

    dim3 g1(G7 / 256, (C_ + 15) / 16);
    tg_kernel<<<g1, 256>>>(emb, Wc, bc);

    cudaFuncSetAttribute(rec_kernel, cudaFuncAttributeMaxDynamicSharedMemorySize, SMEM_BYTES);
    rec_kernel<<<NCTA, NTHR, SMEM_BYTES>>>(marks, ts, Wc, init, out);
}

// round 9
// speedup vs baseline: 1.9261x; 1.9261x over previous
#include <cuda_runtime.h>
#include <cstdint>

#define B_   64
#define T_   512
#define H_   512
#define E_   128
#define C_   1000
#define G7   (7 * H_)    // 3584
#define OUTW (6 * H_)    // 3072
#define NCTA 128
#define NTHR 512

typedef unsigned long long ull;

// ---- device-global scratch ----
__device__ float g_tg[C_ * G7];        // table_gates = emb @ W1 + b   (14.3 MB)
__device__ float g_h[2][H_ * B_];      // h_d double buffer, [buf][k*64+b]
__device__ int           g_count;
__device__ volatile int  g_sense;

// ---- helpers ----
__device__ __forceinline__ float sigf(float x)      { return 1.0f / (1.0f + expf(-x)); }
__device__ __forceinline__ float softplusf(float x) { return fmaxf(x, 0.0f) + log1pf(expf(-fabsf(x))); }

__device__ __forceinline__ void ffma2(ull& d, ull a, ull b)
{
    asm("fma.rn.f32x2 %0, %1, %2, %0;" : "+l"(d) : "l"(a), "l"(b));
}
__device__ __forceinline__ ull dup2(float w)
{
    ull d; unsigned u = __float_as_uint(w);
    asm("mov.b64 %0, {%1, %1};" : "=l"(d) : "r"(u));
    return d;
}
__device__ __forceinline__ uint32_t smem_u32(const void* p)
{
    uint32_t a;
    asm("{ .reg .u64 t; cvta.to.shared.u64 t, %1; cvt.u32.u64 %0, t; }" : "=r"(a) : "l"(p));
    return a;
}
__device__ __forceinline__ void mbar_init(uint32_t mbar, uint32_t cnt)
{
    asm volatile("mbarrier.init.shared.b64 [%0], %1;" :: "r"(mbar), "r"(cnt) : "memory");
}
__device__ __forceinline__ void mbar_expect_tx(uint32_t mbar, uint32_t bytes)
{
    asm volatile("mbarrier.arrive.expect_tx.shared.b64 _, [%0], %1;" :: "r"(mbar), "r"(bytes) : "memory");
}
__device__ __forceinline__ void bulk_ldgsts(uint32_t dst, const void* src, uint32_t bytes, uint32_t mbar)
{
    asm volatile("cp.async.bulk.shared::cta.global.mbarrier::complete_tx::bytes [%0], [%1], %2, [%3];"
                 :: "r"(dst), "l"(src), "r"(bytes), "r"(mbar) : "memory");
}
__device__ __forceinline__ void mbar_wait(uint32_t mbar, uint32_t parity)
{
    uint32_t done;
    asm volatile(
        "{\n\t.reg .pred p;\n\t"
        "mbarrier.try_wait.parity.acquire.cta.shared::cta.b64 p, [%1], %2;\n\t"
        "selp.b32 %0, 1, 0, p;\n\t}"
        : "=r"(done) : "r"(mbar), "r"(parity) : "memory");
    if (!done) {
        asm volatile(
            "{\n\t.reg .pred P1;\n\t"
            "WL_%=:\n\t"
            "mbarrier.try_wait.parity.acquire.cta.shared::cta.b64 P1, [%0], %1, 0x989680;\n\t"
            "@P1 bra.uni WD_%=;\n\t"
            "bra.uni WL_%=;\n\t"
            "WD_%=:\n\t}"
            :: "r"(mbar), "r"(parity) : "memory");
    }
}
__device__ __forceinline__ void fence_proxy_async_()
{
    asm volatile("fence.proxy.async;" ::: "memory");
}

__device__ __forceinline__ void grid_sync(int* sense)
{
    __threadfence();
    __syncthreads();
    if (threadIdx.x == 0) {
        int s = *sense ^ 1;
        *sense = s;
        if (atomicAdd(&g_count, 1) == (int)gridDim.x - 1) {
            g_count = 0;
            __threadfence();
            g_sense = s;
        } else {
            while (g_sense != s) { __nanosleep(64); }
            __threadfence();
        }
    }
    __syncthreads();
}

// =====================  Kernel 1: table_gates  =====================
__global__ void tg_kernel(const float* __restrict__ emb,
                          const float* __restrict__ W,
                          const float* __restrict__ bias)
{
    __shared__ float sh_e[16][E_];
    const int col = blockIdx.x * 256 + threadIdx.x;
    const int c0  = blockIdx.y * 16;

    for (int i = threadIdx.x; i < 16 * E_; i += 256) {
        int ci = i >> 7, e = i & 127;
        int c  = c0 + ci;
        sh_e[ci][e] = (c < C_) ? emb[c * E_ + e] : 0.0f;
    }
    __syncthreads();

    float acc[16];
#pragma unroll
    for (int i = 0; i < 16; ++i) acc[i] = 0.0f;

    for (int e = 0; e < E_; ++e) {
        float wv = W[e * G7 + col];
#pragma unroll
        for (int i = 0; i < 16; ++i) acc[i] = fmaf(sh_e[i][e], wv, acc[i]);
    }
    float bb = bias[col];
#pragma unroll
    for (int i = 0; i < 16; ++i) {
        int c = c0 + i;
        if (c < C_) g_tg[c * G7 + col] = acc[i] + bb;
    }
}

// =====================  Kernel 2: persistent recurrence  =====================
// 128 CTAs x 512 threads. CTA owns j in [4*cta,4*cta+4) (28 gate cols).
// tid = ks*64 + r ; ks 0..7 (K-split 8) ; r = bq*4 + jl.
// Inner loop = R6 core (scalar-W smem broadcast + reg dup2 + FFMA2).
// h(t) staged by cp.async.bulk into 4 SEPARATE 32KB buffers (one per k-chunk),
// issued once per step by thread 0 right after the grid barrier. No empty
// barriers needed: buffer reuse across steps is gated by the grid barrier.
#define WS_F    (512 * 32)            // 16384 floats = 65536 B  (W scalar, [k][jl][g8])
#define HB_F    (128 * 64)            //  8192 floats = 32768 B per buffer
#define HBUF_BYTES 32768
#define RSTRIDE 30                    // floats per reduction record
#define RED_F   (256 * RSTRIDE)       // 7680 floats = 30720 B (tree reduction)
#define MBAR_OFF ((WS_F + 4 * HB_F + RED_F) * 4)     // 227328
#define SMEM_BYTES (MBAR_OFF + 64)                   // 227392

__global__ void __launch_bounds__(NTHR, 1)
rec_kernel(const int*   __restrict__ marks,
           const float* __restrict__ ts,
           const float* __restrict__ Wc,
           const float* __restrict__ init,
           float*       __restrict__ out)
{
    extern __shared__ float smem[];
    float* sh_W   = smem;                         // 64KB
    float* sh_hb  = smem + WS_F;                  // 4 x 32KB
    float* sh_red = sh_hb + 4 * HB_F;             // 30KB
    const uint32_t mb  = smem_u32((char*)smem + MBAR_OFF);  // full[c] = mb + 8c
    const uint32_t hb0 = smem_u32(sh_hb);

    const int tid = threadIdx.x;
    const int cta = blockIdx.x;
    const int ks  = tid >> 6;        // 0..7
    const int r   = tid & 63;
    const int jl  = r & 3;
    const int q4  = (r >> 2) * 4;

    const int eb  = tid >> 2;        // 0..63 (epilogue, tid<256)
    const int ejl = tid & 3;
    const int ej  = cta * 4 + ejl;

    // ---- init mbarriers (arrive count 1: thread 0's expect_tx) ----
    if (tid == 0) {
#pragma unroll
        for (int c = 0; c < 4; ++c) mbar_init(mb + 8 * c, 1);
    }

    // ---- load resident W slice: [k][jl][g pad8] scalar ----
    for (int idx = tid; idx < WS_F; idx += NTHR) {
        int k = idx >> 5; int rem = idx & 31;
        int jj = rem >> 3, g = rem & 7;
        sh_W[idx] = (g < 7) ? Wc[(size_t)(E_ + k) * G7 + g * H_ + cta * 4 + jj] : 0.0f;
    }

    // ---- init h buffer ----
    for (int idx = tid; idx < 4 * 64; idx += NTHR) {
        int jj = idx >> 6, bb = idx & 63;
        g_h[0][(cta * 4 + jj) * B_ + bb] = tanhf(init[cta * 4 + jj]);
    }

    // ---- output row t=0 ----
    for (int idx = tid; idx < 4 * 6 * 64; idx += NTHR) {
        int bb = idx & 63; int rest = idx >> 6;
        int f = rest % 6; int jj = rest / 6;
        int jg = cta * 4 + jj;
        float v;
        switch (f) {
            case 0:  v = tanhf(init[0 * H_ + jg]);     break;
            case 1:  v = sigf (init[5 * H_ + jg]);     break;
            case 2:  v = tanhf(init[2 * H_ + jg]);     break;
            case 3:  v = tanhf(init[3 * H_ + jg]);     break;
            case 4:  v = softplusf(init[4 * H_ + jg]); break;
            default: v = tanhf(init[1 * H_ + jg]);     break;
        }
        out[(size_t)bb * (513 * OUTW) + f * H_ + jg] = v;
    }

    // ---- per-(b,j) recurrent state (epilogue threads) ----
    float c_d = tanhf(init[H_ + ej]);
    float c_b = tanhf(init[2 * H_ + ej]);

    int sense = 0;
    grid_sync(&sense);   // 1 + 511 in-loop = 512 flips (even -> graph replay safe)

    int fph = 0;   // shared phase for all 4 full barriers (each flips once/step)

#define STEP(hp, wp) do {                                                       \
        ull hx = *(const ull*)(hp);                                             \
        ull hy = *(const ull*)((hp) + 2);                                       \
        float4 wA = *(const float4*)(wp);                                       \
        float2 wB = *(const float2*)((wp) + 4);                                 \
        float  wC = (wp)[6];                                                    \
        ull w;                                                                  \
        w = dup2(wA.x); ffma2(acc[0],  w, hx); ffma2(acc[1],  w, hy);           \
        w = dup2(wA.y); ffma2(acc[2],  w, hx); ffma2(acc[3],  w, hy);           \
        w = dup2(wA.z); ffma2(acc[4],  w, hx); ffma2(acc[5],  w, hy);           \
        w = dup2(wA.w); ffma2(acc[6],  w, hx); ffma2(acc[7],  w, hy);           \
        w = dup2(wB.x); ffma2(acc[8],  w, hx); ffma2(acc[9],  w, hy);           \
        w = dup2(wB.y); ffma2(acc[10], w, hx); ffma2(acc[11], w, hy);           \
        w = dup2(wC);   ffma2(acc[12], w, hx); ffma2(acc[13], w, hy);           \
    } while (0)

#define COMPUTE_CHUNK(c) do {                                                   \
        const float* hp = sh_hb + (c) * HB_F + (ks * 16) * 64 + q4;             \
        const float* wp = sh_W + (size_t)((128 * (c) + ks * 16) * 4 + jl) * 8;  \
        _Pragma("unroll 8")                                                     \
        for (int m = 0; m < 16; ++m) { STEP(hp, wp); hp += 64; wp += 32; }      \
    } while (0)

    for (int t = 0; t < T_; ++t) {
        const char* hsrc = (const char*)&g_h[t & 1][0];

        // ---- thread 0: stage all four h chunks (grid barrier already passed) ----
        if (tid == 0) {
            fence_proxy_async_();
#pragma unroll
            for (int c = 0; c < 4; ++c) {
                mbar_expect_tx(mb + 8 * c, HBUF_BYTES);
                bulk_ldgsts(hb0 + c * HBUF_BYTES, hsrc + c * HBUF_BYTES, HBUF_BYTES, mb + 8 * c);
            }
        }

        // ---- epilogue prefetch (long-latency, consumed after matmul) ----
        float tsv = 0.f, tsp = 0.f, tg[7];
        if (tid < 256) {
            int m = __ldg(&marks[eb * T_ + t]);
            tsv   = __ldg(&ts[eb * T_ + t]);
            tsp   = (t > 0) ? __ldg(&ts[eb * T_ + t - 1]) : 0.0f;
            const float* tgp = g_tg + (size_t)m * G7 + ej;
#pragma unroll
            for (int g = 0; g < 7; ++g) tg[g] = __ldcg(tgp + g * H_);
        }

        ull acc[14];
#pragma unroll
        for (int i = 0; i < 14; ++i) acc[i] = 0ull;

        mbar_wait(mb + 0,  fph); COMPUTE_CHUNK(0);
        mbar_wait(mb + 8,  fph); COMPUTE_CHUNK(1);
        mbar_wait(mb + 16, fph); COMPUTE_CHUNK(2);
        mbar_wait(mb + 24, fph); COMPUTE_CHUNK(3);
        fph ^= 1;

        // ---- tree reduction: round 1 (upper half writes) ----
        if (tid >= 256) {
            ull* rb = (ull*)(sh_red + (size_t)(tid - 256) * RSTRIDE);
#pragma unroll
            for (int i = 0; i < 14; ++i) rb[i] = acc[i];
        }
        __syncthreads();

        // ---- round 2: lower half adds partner, rewrites record ----
        if (tid < 256) {
            float2* af = (float2*)acc;
            const float2* rp = (const float2*)(sh_red + (size_t)tid * RSTRIDE);
#pragma unroll
            for (int i = 0; i < 14; ++i) {
                float2 v = rp[i];
                af[i].x += v.x; af[i].y += v.y;
            }
            ull* rb = (ull*)(sh_red + (size_t)tid * RSTRIDE);
#pragma unroll
            for (int i = 0; i < 14; ++i) rb[i] = acc[i];
        }
        __syncthreads();

        // ---- epilogue: 256 threads, one (b,j) each ----
        float go = 0.f, cb = 0.f, c = 0.f, gd = 0.f, cd = 0.f, hd = 0.f;
        if (tid < 256) {
            const int r_src = ((eb >> 2) << 2) | ejl;
            const int fidx  = eb & 3;
            float a[7];
#pragma unroll
            for (int g = 0; g < 7; ++g) a[g] = 0.0f;
#pragma unroll
            for (int s = 0; s < 4; ++s) {
                const float* rp = sh_red + (size_t)(s * 64 + r_src) * RSTRIDE;
#pragma unroll
                for (int g = 0; g < 7; ++g) a[g] += rp[g * 4 + fidx];
            }

            float dur = tsv - tsp;
            float gi  = sigf (a[0] + tg[0]);
            float gf  = sigf (a[1] + tg[1]);
            float gz  = tanhf(a[2] + tg[2]);
            go  = sigf (a[3] + tg[3]);
            float gib = sigf (a[4] + tg[4]);
            float gfb = sigf (a[5] + tg[5]);
            gd  = softplusf(a[6] + tg[6]);

            c  = gf * c_d + gi * gz;
            cb = gfb * c_b + gib * gz;
            cd = cb + (c - cb) * expf(-gd * dur);
            hd = go * tanhf(cd);
            c_d = cd; c_b = cb;

            g_h[(t + 1) & 1][ej * B_ + eb] = hd;   // publish h first
        }

        // ---- split grid barrier: arrive, then hide output STGs under the wait ----
        const bool last = (t == T_ - 1);
        int s_loc = 0;
        __threadfence();
        __syncthreads();
        if (tid == 0 && !last) {
            s_loc = sense ^ 1; sense = s_loc;
            if (atomicAdd(&g_count, 1) == (int)gridDim.x - 1) {
                g_count = 0;
                __threadfence();
                g_sense = s_loc;
            }
        }

        if (tid < 256) {
            size_t ob = (size_t)eb * (513 * OUTW) + (size_t)(t + 1) * OUTW + ej;
            out[ob]          = hd;
            out[ob + 1 * H_] = go;
            out[ob + 2 * H_] = cb;
            out[ob + 3 * H_] = c;
            out[ob + 4 * H_] = gd;
            out[ob + 5 * H_] = cd;
        }

        if (!last) {
            if (tid == 0) {
                while (g_sense != s_loc) { __nanosleep(64); }
                __threadfence();
            }
            __syncthreads();
        }
    }
#undef COMPUTE_CHUNK
#undef STEP
}

// =====================  launch  =====================
extern "C" void kernel_launch(void* const* d_in, const int* in_sizes, int n_in,
                              void* d_out, int out_size)
{
    const int*   marks = (const int*)  d_in[0];
    const float* ts    = (const float*)d_in[1];
    const float* emb   = (const float*)d_in[2];
    const float* Wc    = (const float*)d_in[3];
    const float* bc    = (const float*)d_in[4];
    const float* init  = (const float*)d_in[5];
    float*       out   = (float*)d_out;

    dim3 g1(G7 / 256, (C_ + 15) / 16);
    tg_kernel<<<g1, 256>>>(emb, Wc, bc);

    cudaFuncSetAttribute(rec_kernel, cudaFuncAttributeMaxDynamicSharedMemorySize, SMEM_BYTES);
    rec_kernel<<<NCTA, NTHR, SMEM_BYTES>>>(marks, ts, Wc, init, out);
}